// round 6
// baseline (speedup 1.0000x reference)
#include <cuda_runtime.h>
#include <cuda_bf16.h>
#include <cstdint>

// out[b,i,j] = Vx(i; t0,t2) * Vy(j; t1,t2), with
//   t = x @ (W1@W2) + (b1@W2 + b2)   (the two linears collapse)
// Kernel A builds Weff[1024,3] (split into 3 arrays) + beff[3].
// Kernel B: warp per batch row -> skinny GEMV -> boxcar outer product,
// rasterized with float4 stores (output write is the DRAM floor: 205 MB).

#define MAX_D 1024
#define MAX_H 512
#define S 56
#define KSTEEP 10.0f

__device__ float g_w0[MAX_D];
__device__ float g_w1[MAX_D];
__device__ float g_w2[MAX_D];
__device__ float g_beff[3];

// ---------------------------------------------------------------------------
// Kernel A: Weff = W1 @ W2 (warp per d-row, W2 staged in smem),
//           beff = b1 @ W2 + b2 (warp-parallel, block 0 warp 0 extra duty).
// ---------------------------------------------------------------------------
__global__ __launch_bounds__(256) void weff_kernel(const float* __restrict__ W1,
                                                   const float* __restrict__ b1,
                                                   const float* __restrict__ W2,
                                                   const float* __restrict__ b2,
                                                   int D, int H) {
    __shared__ float s_W2[MAX_H * 3];

    const int nW2 = H * 3;
    for (int idx = threadIdx.x; idx < nW2; idx += blockDim.x)
        s_W2[idx] = W2[idx];
    __syncthreads();

    const int lane = threadIdx.x & 31;
    const int warp = (blockIdx.x * blockDim.x + threadIdx.x) >> 5;

    if (warp < D) {
        const float* __restrict__ row = W1 + (size_t)warp * H;
        float a0 = 0.f, a1 = 0.f, a2 = 0.f;
        #pragma unroll 4
        for (int h = lane; h < H; h += 32) {
            float w = row[h];                 // coalesced LDG
            a0 = fmaf(w, s_W2[h * 3 + 0], a0);  // conflict-free (3 coprime 32)
            a1 = fmaf(w, s_W2[h * 3 + 1], a1);
            a2 = fmaf(w, s_W2[h * 3 + 2], a2);
        }
        #pragma unroll
        for (int o = 16; o > 0; o >>= 1) {
            a0 += __shfl_xor_sync(0xffffffffu, a0, o);
            a1 += __shfl_xor_sync(0xffffffffu, a1, o);
            a2 += __shfl_xor_sync(0xffffffffu, a2, o);
        }
        if (lane == 0) {
            g_w0[warp] = a0;
            g_w1[warp] = a1;
            g_w2[warp] = a2;
        }
    }

    // beff: one warp, strided + shfl reduce
    if (blockIdx.x == 0 && threadIdx.x < 32) {
        float s0 = 0.f, s1 = 0.f, s2 = 0.f;
        for (int h = lane; h < H; h += 32) {
            float bv = b1[h];
            s0 = fmaf(bv, s_W2[h * 3 + 0], s0);
            s1 = fmaf(bv, s_W2[h * 3 + 1], s1);
            s2 = fmaf(bv, s_W2[h * 3 + 2], s2);
        }
        #pragma unroll
        for (int o = 16; o > 0; o >>= 1) {
            s0 += __shfl_xor_sync(0xffffffffu, s0, o);
            s1 += __shfl_xor_sync(0xffffffffu, s1, o);
            s2 += __shfl_xor_sync(0xffffffffu, s2, o);
        }
        if (lane == 0) {
            g_beff[0] = s0 + b2[0];
            g_beff[1] = s1 + b2[1];
            g_beff[2] = s2 + b2[2];
        }
    }
}

// ---------------------------------------------------------------------------
// Kernel B
// ---------------------------------------------------------------------------
__device__ __forceinline__ float fsigmoid(float z) {
    return 1.0f / (1.0f + __expf(-z));
}

#define WARPS_PER_BLK 8

__global__ __launch_bounds__(WARPS_PER_BLK * 32) void boxcar_kernel(
        const float* __restrict__ x, float* __restrict__ out, int B, int D) {
    __shared__ float s_w0[MAX_D];
    __shared__ float s_w1[MAX_D];
    __shared__ float s_w2[MAX_D];
    __shared__ float s_vx[WARPS_PER_BLK][64];   // 64 for float4 alignment/padding
    __shared__ float s_vy[WARPS_PER_BLK][64];

    for (int e = threadIdx.x; e < D; e += blockDim.x) {
        s_w0[e] = g_w0[e];
        s_w1[e] = g_w1[e];
        s_w2[e] = g_w2[e];
    }
    __syncthreads();

    const int lane = threadIdx.x & 31;
    const int wid  = threadIdx.x >> 5;
    const int row  = blockIdx.x * WARPS_PER_BLK + wid;
    if (row >= B) return;

    // ---- skinny GEMV, float4-vectorized: D/4 chunks, 32 lanes ----
    const float4* __restrict__ x4 = (const float4*)(x + (size_t)row * D);
    const int nchunks = D >> 2;                 // 256 for D=1024
    float a0 = 0.f, a1 = 0.f, a2 = 0.f;
    #pragma unroll 4
    for (int c = lane; c < nchunks; c += 32) {
        float4 xv = x4[c];                      // coalesced LDG.128
        int e = c << 2;
        float4 w0 = *(const float4*)&s_w0[e];
        float4 w1 = *(const float4*)&s_w1[e];
        float4 w2 = *(const float4*)&s_w2[e];
        a0 = fmaf(xv.x, w0.x, fmaf(xv.y, w0.y, fmaf(xv.z, w0.z, fmaf(xv.w, w0.w, a0))));
        a1 = fmaf(xv.x, w1.x, fmaf(xv.y, w1.y, fmaf(xv.z, w1.z, fmaf(xv.w, w1.w, a1))));
        a2 = fmaf(xv.x, w2.x, fmaf(xv.y, w2.y, fmaf(xv.z, w2.z, fmaf(xv.w, w2.w, a2))));
    }
    #pragma unroll
    for (int o = 16; o > 0; o >>= 1) {
        a0 += __shfl_xor_sync(0xffffffffu, a0, o);
        a1 += __shfl_xor_sync(0xffffffffu, a1, o);
        a2 += __shfl_xor_sync(0xffffffffu, a2, o);
    }
    const float t0 = a0 + g_beff[0];
    const float t1 = a1 + g_beff[1];
    const float t2 = a2 + g_beff[2];

    // ---- per-warp boxcar profiles into smem (coords lane and lane+32) ----
    const float half = 0.5f * t2;
    {
        const float c0 = (float)lane;
        s_vx[wid][lane] = fsigmoid(KSTEEP * (c0 - t0 + half))
                        - fsigmoid(KSTEEP * (c0 - t0 - half));
        s_vy[wid][lane] = fsigmoid(KSTEEP * (c0 - t1 + half))
                        - fsigmoid(KSTEEP * (c0 - t1 - half));
        if (lane < S - 32) {
            const float c1 = (float)(lane + 32);
            s_vx[wid][lane + 32] = fsigmoid(KSTEEP * (c1 - t0 + half))
                                 - fsigmoid(KSTEEP * (c1 - t0 - half));
            s_vy[wid][lane + 32] = fsigmoid(KSTEEP * (c1 - t1 + half))
                                 - fsigmoid(KSTEEP * (c1 - t1 - half));
        }
    }
    __syncwarp();

    // ---- rasterize outer product as flat float4 stream ----
    // 56*56 = 3136 floats = 784 float4; k -> (i = k/14, j = (k%14)*4)
    float4* __restrict__ o4 = (float4*)(out + (size_t)row * (S * S));
    const float* __restrict__ vx = s_vx[wid];
    const float* __restrict__ vy = s_vy[wid];
    #pragma unroll 4
    for (int k = lane; k < (S * S) / 4; k += 32) {
        int i  = k / 14;
        int jj = (k - i * 14) << 2;
        float vxi = vx[i];
        float4 v4 = *(const float4*)&vy[jj];
        float4 r;
        r.x = vxi * v4.x;
        r.y = vxi * v4.y;
        r.z = vxi * v4.z;
        r.w = vxi * v4.w;
        o4[k] = r;                              // STG.128
    }
}

// ---------------------------------------------------------------------------
// Launch. Inputs: x[B,D], W1[D,H], b1[H], W2[H,3], b2[3]. Output: [B,56,56] f32.
// ---------------------------------------------------------------------------
extern "C" void kernel_launch(void* const* d_in, const int* in_sizes, int n_in,
                              void* d_out, int out_size) {
    const float* x  = (const float*)d_in[0];
    const float* W1 = (const float*)d_in[1];
    const float* b1 = (const float*)d_in[2];
    const float* W2 = (const float*)d_in[3];
    const float* b2 = (const float*)d_in[4];
    float* out = (float*)d_out;

    const int H = in_sizes[2];           // 512
    const int D = in_sizes[1] / H;       // 1024
    const int B = in_sizes[0] / D;       // 16384

    {
        int threads = 256;
        int blocks = (D * 32 + threads - 1) / threads;   // warp per d-row
        weff_kernel<<<blocks, threads>>>(W1, b1, W2, b2, D, H);
    }
    {
        int threads = WARPS_PER_BLK * 32;
        int blocks = (B + WARPS_PER_BLK - 1) / WARPS_PER_BLK;
        boxcar_kernel<<<blocks, threads>>>(x, out, B, D);
    }
}

// round 7
// speedup vs baseline: 1.3398x; 1.3398x over previous
#include <cuda_runtime.h>
#include <cuda_bf16.h>
#include <cstdint>

// out[b,i,j] = Vx(i; t0,t2) * Vy(j; t1,t2), with
//   t = x @ (W1@W2) + (b1@W2 + b2)   (the two linears collapse)
// Kernel A builds Weff[1024,3] (split arrays) + beff[3], with W2 staged in
// smem (the R4 version had a 32-way sector fan-out on W2 loads -> ~20us).
// Kernel B is the proven R4 rasterizer: warp per batch row, shfl-broadcast
// outer product, contiguous row stores. Output write (205 MB) is the floor.

#define MAX_D 1024
#define MAX_H 512
#define S 56
#define KSTEEP 10.0f

__device__ float g_w0[MAX_D];
__device__ float g_w1[MAX_D];
__device__ float g_w2[MAX_D];
__device__ float g_beff[3];

// ---------------------------------------------------------------------------
// Kernel A: Weff = W1 @ W2 (warp per d-row, W2 staged in smem),
//           beff = b1 @ W2 + b2 (one warp in block 0).
// ---------------------------------------------------------------------------
__global__ __launch_bounds__(256) void weff_kernel(const float* __restrict__ W1,
                                                   const float* __restrict__ b1,
                                                   const float* __restrict__ W2,
                                                   const float* __restrict__ b2,
                                                   int D, int H) {
    __shared__ float s_W2[MAX_H * 3];

    const int nW2 = H * 3;
    for (int idx = threadIdx.x; idx < nW2; idx += blockDim.x)
        s_W2[idx] = W2[idx];
    __syncthreads();

    const int lane = threadIdx.x & 31;
    const int warp = (blockIdx.x * blockDim.x + threadIdx.x) >> 5;

    if (warp < D) {
        const float* __restrict__ row = W1 + (size_t)warp * H;
        float a0 = 0.f, a1 = 0.f, a2 = 0.f;
        #pragma unroll 4
        for (int h = lane; h < H; h += 32) {
            float w = row[h];                   // coalesced LDG
            a0 = fmaf(w, s_W2[h * 3 + 0], a0);  // stride-3 LDS: conflict-free
            a1 = fmaf(w, s_W2[h * 3 + 1], a1);
            a2 = fmaf(w, s_W2[h * 3 + 2], a2);
        }
        #pragma unroll
        for (int o = 16; o > 0; o >>= 1) {
            a0 += __shfl_xor_sync(0xffffffffu, a0, o);
            a1 += __shfl_xor_sync(0xffffffffu, a1, o);
            a2 += __shfl_xor_sync(0xffffffffu, a2, o);
        }
        if (lane == 0) {
            g_w0[warp] = a0;
            g_w1[warp] = a1;
            g_w2[warp] = a2;
        }
    }

    // beff: one warp, strided + shfl reduce
    if (blockIdx.x == 0 && threadIdx.x < 32) {
        float s0 = 0.f, s1 = 0.f, s2 = 0.f;
        for (int h = lane; h < H; h += 32) {
            float bv = b1[h];
            s0 = fmaf(bv, s_W2[h * 3 + 0], s0);
            s1 = fmaf(bv, s_W2[h * 3 + 1], s1);
            s2 = fmaf(bv, s_W2[h * 3 + 2], s2);
        }
        #pragma unroll
        for (int o = 16; o > 0; o >>= 1) {
            s0 += __shfl_xor_sync(0xffffffffu, s0, o);
            s1 += __shfl_xor_sync(0xffffffffu, s1, o);
            s2 += __shfl_xor_sync(0xffffffffu, s2, o);
        }
        if (lane == 0) {
            g_beff[0] = s0 + b2[0];
            g_beff[1] = s1 + b2[1];
            g_beff[2] = s2 + b2[2];
        }
    }
}

// ---------------------------------------------------------------------------
// Kernel B: one warp per batch row (proven R4 structure).
// ---------------------------------------------------------------------------
__device__ __forceinline__ float fsigmoid(float z) {
    return 1.0f / (1.0f + __expf(-z));
}

__global__ __launch_bounds__(256) void boxcar_kernel(const float* __restrict__ x,
                                                     float* __restrict__ out,
                                                     int B, int D) {
    __shared__ float s_w0[MAX_D];
    __shared__ float s_w1[MAX_D];
    __shared__ float s_w2[MAX_D];

    for (int e = threadIdx.x; e < D; e += blockDim.x) {
        s_w0[e] = g_w0[e];
        s_w1[e] = g_w1[e];
        s_w2[e] = g_w2[e];
    }
    __syncthreads();

    const int lane = threadIdx.x & 31;
    const int wid  = threadIdx.x >> 5;
    const int row  = blockIdx.x * (blockDim.x >> 5) + wid;
    if (row >= B) return;

    // ---- skinny GEMV: 3 dot products over D, conflict-free smem weights ----
    const float* __restrict__ xr = x + (size_t)row * D;
    float a0 = 0.f, a1 = 0.f, a2 = 0.f;
    #pragma unroll 8
    for (int e = lane; e < D; e += 32) {
        float xv = xr[e];
        a0 = fmaf(xv, s_w0[e], a0);
        a1 = fmaf(xv, s_w1[e], a1);
        a2 = fmaf(xv, s_w2[e], a2);
    }
    #pragma unroll
    for (int o = 16; o > 0; o >>= 1) {
        a0 += __shfl_xor_sync(0xffffffffu, a0, o);
        a1 += __shfl_xor_sync(0xffffffffu, a1, o);
        a2 += __shfl_xor_sync(0xffffffffu, a2, o);
    }
    const float t0 = a0 + g_beff[0];   // x center (maps to i)
    const float t1 = a1 + g_beff[1];   // y center (maps to j)
    const float t2 = a2 + g_beff[2];   // size

    // ---- boxcar profiles: lane covers coords lane and lane+32 ----
    const float half = 0.5f * t2;
    const float c0 = (float)lane;
    const float c1 = (float)(lane + 32);

    float vx0 = fsigmoid(KSTEEP * (c0 - t0 + half)) - fsigmoid(KSTEEP * (c0 - t0 - half));
    float vy0 = fsigmoid(KSTEEP * (c0 - t1 + half)) - fsigmoid(KSTEEP * (c0 - t1 - half));
    float vx1 = 0.f, vy1 = 0.f;
    if (lane < S - 32) {
        vx1 = fsigmoid(KSTEEP * (c1 - t0 + half)) - fsigmoid(KSTEEP * (c1 - t0 - half));
        vy1 = fsigmoid(KSTEEP * (c1 - t1 + half)) - fsigmoid(KSTEEP * (c1 - t1 - half));
    }

    // ---- rasterize outer product: 56 rows of 56 contiguous floats ----
    float* __restrict__ orow = out + (size_t)row * (S * S);
    #pragma unroll
    for (int i = 0; i < S; i++) {
        float src = (i < 32) ? vx0 : vx1;
        float vxi = __shfl_sync(0xffffffffu, src, i & 31);
        orow[lane] = vxi * vy0;
        if (lane < S - 32)
            orow[lane + 32] = vxi * vy1;
        orow += S;
    }
}

// ---------------------------------------------------------------------------
// Launch. Inputs: x[B,D], W1[D,H], b1[H], W2[H,3], b2[3]. Output: [B,56,56] f32.
// ---------------------------------------------------------------------------
extern "C" void kernel_launch(void* const* d_in, const int* in_sizes, int n_in,
                              void* d_out, int out_size) {
    const float* x  = (const float*)d_in[0];
    const float* W1 = (const float*)d_in[1];
    const float* b1 = (const float*)d_in[2];
    const float* W2 = (const float*)d_in[3];
    const float* b2 = (const float*)d_in[4];
    float* out = (float*)d_out;

    const int H = in_sizes[2];           // 512
    const int D = in_sizes[1] / H;       // 1024
    const int B = in_sizes[0] / D;       // 16384

    {
        int threads = 256;
        int blocks = (D * 32 + threads - 1) / threads;   // warp per d-row
        weff_kernel<<<blocks, threads>>>(W1, b1, W2, b2, D, H);
    }
    {
        int threads = 256;
        int rows_per_block = threads / 32;
        int blocks = (B + rows_per_block - 1) / rows_per_block;
        boxcar_kernel<<<blocks, threads>>>(x, out, B, D);
    }
}

// round 8
// speedup vs baseline: 1.3775x; 1.0281x over previous
#include <cuda_runtime.h>
#include <cuda_bf16.h>
#include <cstdint>

// out[b,i,j] = Vx(i; t0,t2) * Vy(j; t1,t2), with
//   t = x @ (W1@W2) + (b1@W2 + b2)   (the two linears collapse)
// Kernel A: Weff[1024,3] (split arrays) + beff[3], W2 staged in smem.
// Kernel B: warp per batch row -> float4 GEMV -> boxcar outer product,
//           rasterized with one predicated STG.64 per output row.
// Theory: kernel B is MIO issue-slot bound; halve store instrs, quarter
// GEMV load instrs, keep the proven shfl-broadcast structure.

#define MAX_D 1024
#define MAX_H 512
#define S 56
#define KSTEEP 10.0f

__device__ float g_w0[MAX_D];
__device__ float g_w1[MAX_D];
__device__ float g_w2[MAX_D];
__device__ float g_beff[3];

// ---------------------------------------------------------------------------
// Kernel A: Weff = W1 @ W2 (warp per d-row, W2 staged in smem),
//           beff = b1 @ W2 + b2 (one warp in block 0).
// ---------------------------------------------------------------------------
__global__ __launch_bounds__(256) void weff_kernel(const float* __restrict__ W1,
                                                   const float* __restrict__ b1,
                                                   const float* __restrict__ W2,
                                                   const float* __restrict__ b2,
                                                   int D, int H) {
    __shared__ float s_W2[MAX_H * 3];

    const int nW2 = H * 3;
    for (int idx = threadIdx.x; idx < nW2; idx += blockDim.x)
        s_W2[idx] = W2[idx];
    __syncthreads();

    const int lane = threadIdx.x & 31;
    const int warp = (blockIdx.x * blockDim.x + threadIdx.x) >> 5;

    if (warp < D) {
        const float4* __restrict__ row4 = (const float4*)(W1 + (size_t)warp * H);
        const int nch = H >> 2;                 // 128 for H=512
        float a0 = 0.f, a1 = 0.f, a2 = 0.f;
        #pragma unroll 4
        for (int c = lane; c < nch; c += 32) {
            float4 w = row4[c];                 // LDG.128, coalesced
            int h = c << 2;
            a0 = fmaf(w.x, s_W2[(h+0)*3+0], fmaf(w.y, s_W2[(h+1)*3+0],
                 fmaf(w.z, s_W2[(h+2)*3+0], fmaf(w.w, s_W2[(h+3)*3+0], a0))));
            a1 = fmaf(w.x, s_W2[(h+0)*3+1], fmaf(w.y, s_W2[(h+1)*3+1],
                 fmaf(w.z, s_W2[(h+2)*3+1], fmaf(w.w, s_W2[(h+3)*3+1], a1))));
            a2 = fmaf(w.x, s_W2[(h+0)*3+2], fmaf(w.y, s_W2[(h+1)*3+2],
                 fmaf(w.z, s_W2[(h+2)*3+2], fmaf(w.w, s_W2[(h+3)*3+2], a2))));
        }
        #pragma unroll
        for (int o = 16; o > 0; o >>= 1) {
            a0 += __shfl_xor_sync(0xffffffffu, a0, o);
            a1 += __shfl_xor_sync(0xffffffffu, a1, o);
            a2 += __shfl_xor_sync(0xffffffffu, a2, o);
        }
        if (lane == 0) {
            g_w0[warp] = a0;
            g_w1[warp] = a1;
            g_w2[warp] = a2;
        }
    }

    // beff: one warp, strided + shfl reduce
    if (blockIdx.x == 0 && threadIdx.x < 32) {
        float s0 = 0.f, s1 = 0.f, s2 = 0.f;
        for (int h = lane; h < H; h += 32) {
            float bv = b1[h];
            s0 = fmaf(bv, s_W2[h * 3 + 0], s0);
            s1 = fmaf(bv, s_W2[h * 3 + 1], s1);
            s2 = fmaf(bv, s_W2[h * 3 + 2], s2);
        }
        #pragma unroll
        for (int o = 16; o > 0; o >>= 1) {
            s0 += __shfl_xor_sync(0xffffffffu, s0, o);
            s1 += __shfl_xor_sync(0xffffffffu, s1, o);
            s2 += __shfl_xor_sync(0xffffffffu, s2, o);
        }
        if (lane == 0) {
            g_beff[0] = s0 + b2[0];
            g_beff[1] = s1 + b2[1];
            g_beff[2] = s2 + b2[2];
        }
    }
}

// ---------------------------------------------------------------------------
// Kernel B: one warp per batch row.
// ---------------------------------------------------------------------------
__device__ __forceinline__ float fsigmoid(float z) {
    return 1.0f / (1.0f + __expf(-z));
}

__global__ __launch_bounds__(256) void boxcar_kernel(const float* __restrict__ x,
                                                     float* __restrict__ out,
                                                     int B, int D) {
    __shared__ __align__(16) float s_w0[MAX_D];
    __shared__ __align__(16) float s_w1[MAX_D];
    __shared__ __align__(16) float s_w2[MAX_D];

    for (int e = threadIdx.x; e < D; e += blockDim.x) {
        s_w0[e] = g_w0[e];
        s_w1[e] = g_w1[e];
        s_w2[e] = g_w2[e];
    }
    __syncthreads();

    const int lane = threadIdx.x & 31;
    const int wid  = threadIdx.x >> 5;
    const int row  = blockIdx.x * (blockDim.x >> 5) + wid;
    if (row >= B) return;

    // ---- skinny GEMV, float4-vectorized: 8 LDG.128 + 24 LDS.128 per lane ----
    const float4* __restrict__ x4 = (const float4*)(x + (size_t)row * D);
    const int nch = D >> 2;                     // 256 for D=1024
    float a0 = 0.f, a1 = 0.f, a2 = 0.f;
    #pragma unroll 4
    for (int c = lane; c < nch; c += 32) {
        float4 xv = x4[c];                      // LDG.128, coalesced
        int e = c << 2;
        float4 w0 = *(const float4*)&s_w0[e];
        float4 w1 = *(const float4*)&s_w1[e];
        float4 w2 = *(const float4*)&s_w2[e];
        a0 = fmaf(xv.x, w0.x, fmaf(xv.y, w0.y, fmaf(xv.z, w0.z, fmaf(xv.w, w0.w, a0))));
        a1 = fmaf(xv.x, w1.x, fmaf(xv.y, w1.y, fmaf(xv.z, w1.z, fmaf(xv.w, w1.w, a1))));
        a2 = fmaf(xv.x, w2.x, fmaf(xv.y, w2.y, fmaf(xv.z, w2.z, fmaf(xv.w, w2.w, a2))));
    }
    #pragma unroll
    for (int o = 16; o > 0; o >>= 1) {
        a0 += __shfl_xor_sync(0xffffffffu, a0, o);
        a1 += __shfl_xor_sync(0xffffffffu, a1, o);
        a2 += __shfl_xor_sync(0xffffffffu, a2, o);
    }
    const float t0 = a0 + g_beff[0];   // x center (maps to i)
    const float t1 = a1 + g_beff[1];   // y center (maps to j)
    const float t2 = a2 + g_beff[2];   // size

    // ---- boxcar profiles: lane covers coords lane and lane+32 ----
    const float half = 0.5f * t2;
    const float c0 = (float)lane;
    const float c1 = (float)(lane + 32);

    float vx0 = fsigmoid(KSTEEP * (c0 - t0 + half)) - fsigmoid(KSTEEP * (c0 - t0 - half));
    float vy0 = fsigmoid(KSTEEP * (c0 - t1 + half)) - fsigmoid(KSTEEP * (c0 - t1 - half));
    float vx1 = 0.f, vy1 = 0.f;
    if (lane < S - 32) {
        vx1 = fsigmoid(KSTEEP * (c1 - t0 + half)) - fsigmoid(KSTEEP * (c1 - t0 - half));
        vy1 = fsigmoid(KSTEEP * (c1 - t1 + half)) - fsigmoid(KSTEEP * (c1 - t1 - half));
    }

    // ---- gather vy pair for this lane: vy[2*lane], vy[2*lane+1] (lanes 0-27) ----
    const int e_idx = 2 * lane;
    const int o_idx = 2 * lane + 1;
    float eA = __shfl_sync(0xffffffffu, vy0, e_idx & 31);
    float eB = __shfl_sync(0xffffffffu, vy1, e_idx & 31);
    float oA = __shfl_sync(0xffffffffu, vy0, o_idx & 31);
    float oB = __shfl_sync(0xffffffffu, vy1, o_idx & 31);
    const float vyA = (e_idx < 32) ? eA : eB;
    const float vyB = (o_idx < 32) ? oA : oB;

    // ---- rasterize outer product: one STG.64 per output row (lanes 0-27) ----
    float2* __restrict__ o2 = (float2*)(out + (size_t)row * (S * S));
    #pragma unroll
    for (int i = 0; i < S; i++) {
        float src = (i < 32) ? vx0 : vx1;
        float vxi = __shfl_sync(0xffffffffu, src, i & 31);
        if (lane < S / 2) {
            float2 r;
            r.x = vxi * vyA;
            r.y = vxi * vyB;
            o2[lane] = r;                       // STG.64, 224B/row contiguous
        }
        o2 += S / 2;
    }
}

// ---------------------------------------------------------------------------
// Launch. Inputs: x[B,D], W1[D,H], b1[H], W2[H,3], b2[3]. Output: [B,56,56] f32.
// ---------------------------------------------------------------------------
extern "C" void kernel_launch(void* const* d_in, const int* in_sizes, int n_in,
                              void* d_out, int out_size) {
    const float* x  = (const float*)d_in[0];
    const float* W1 = (const float*)d_in[1];
    const float* b1 = (const float*)d_in[2];
    const float* W2 = (const float*)d_in[3];
    const float* b2 = (const float*)d_in[4];
    float* out = (float*)d_out;

    const int H = in_sizes[2];           // 512
    const int D = in_sizes[1] / H;       // 1024
    const int B = in_sizes[0] / D;       // 16384

    {
        int threads = 256;
        int blocks = (D * 32 + threads - 1) / threads;   // warp per d-row
        weff_kernel<<<blocks, threads>>>(W1, b1, W2, b2, D, H);
    }
    {
        int threads = 256;
        int rows_per_block = threads / 32;
        int blocks = (B + rows_per_block - 1) / rows_per_block;
        boxcar_kernel<<<blocks, threads>>>(x, out, B, D);
    }
}